// round 14
// baseline (speedup 1.0000x reference)
#include <cuda_runtime.h>
#include <cuda_bf16.h>
#include <cstdint>

#define DMODEL 1024
#define NSEQ   1024
static const int MN = DMODEL * NSEQ;

// ---------------- scratch (device globals; no allocs allowed) ----------------
__device__ __nv_bfloat16 g_Q[2 * 1024 * 1024];   // Q [c][n] bf16
__device__ __nv_bfloat16 g_K[2 * 1024 * 1024];   // K [c][n] bf16
__device__ __nv_bfloat16 g_V[2 * 1024 * 1024];   // V [c][n] bf16
__device__ __nv_bfloat16 g_X[2 * 1024 * 1024];   // X^T per item: [n][c] bf16
__device__ __nv_bfloat16 g_W[4 * 1024 * 1024];   // weights bf16 [m][k]
__device__ __nv_bfloat16 g_D[2 * 1024 * 1024];   // desc^T bf16 [n][c]
__device__ __nv_bfloat16 g_T[2 * 1024 * 1024];   // out^T bf16 mirrors [n][c]

__device__ __forceinline__ float ex2f(float x) {
    float y;
    asm("ex2.approx.f32 %0, %1;" : "=f"(y) : "f"(x));
    return y;
}
__device__ __forceinline__ void mma_bf16(float* d, const uint32_t* a, uint32_t b0, uint32_t b1) {
    asm volatile(
        "mma.sync.aligned.m16n8k16.row.col.f32.bf16.bf16.f32 "
        "{%0,%1,%2,%3}, {%4,%5,%6,%7}, {%8,%9}, {%0,%1,%2,%3};"
        : "+f"(d[0]), "+f"(d[1]), "+f"(d[2]), "+f"(d[3])
        : "r"(a[0]), "r"(a[1]), "r"(a[2]), "r"(a[3]), "r"(b0), "r"(b1));
}
__device__ __forceinline__ void ldsm4(uint32_t& r0, uint32_t& r1, uint32_t& r2, uint32_t& r3,
                                      uint32_t addr) {
    asm volatile("ldmatrix.sync.aligned.m8n8.x4.shared.b16 {%0,%1,%2,%3}, [%4];"
                 : "=r"(r0), "=r"(r1), "=r"(r2), "=r"(r3) : "r"(addr));
}
__device__ __forceinline__ void cp16(uint32_t dst, const void* src) {
    asm volatile("cp.async.cg.shared.global [%0], [%1], 16;" :: "r"(dst), "l"(src));
}
#define CP_COMMIT() asm volatile("cp.async.commit_group;")
#define CP_WAIT0()  asm volatile("cp.async.wait_group 0;")

__device__ __forceinline__ __nv_bfloat162 bf2(float lo, float hi) {
    __nv_bfloat162 t;
    t.x = __float2bfloat16_rn(lo);
    t.y = __float2bfloat16_rn(hi);
    return t;
}
__device__ __forceinline__ uint32_t packbf(float lo, float hi) {
    uint32_t r;
    asm("cvt.rn.bf16x2.f32 %0, %1, %2;" : "=r"(r) : "f"(hi), "f"(lo));
    return r;
}

// ---------------- prep: bf16-round weights; transpose+round descs ------------
struct CvtBatch { const float* s[4]; __nv_bfloat16* d[4]; };

__global__ __launch_bounds__(256) void prep_round(CvtBatch cb) {
    const float4* s = (const float4*)cb.s[blockIdx.y];
    __nv_bfloat162* d = (__nv_bfloat162*)cb.d[blockIdx.y];
    int i = blockIdx.x * 256 + threadIdx.x;
    float4 v = s[i];
    d[2 * i]     = bf2(v.x, v.y);
    d[2 * i + 1] = bf2(v.z, v.w);
}

struct CvtTBatch { const float* s[2]; __nv_bfloat16* d[2]; };

// dst[n][c] = bf16(src[c][n])
__global__ __launch_bounds__(256) void prep_round_T(CvtTBatch cb) {
    __shared__ float t[32][33];
    const float* src = cb.s[blockIdx.z];
    __nv_bfloat16* dst = cb.d[blockIdx.z];
    int tx = threadIdx.x & 31, ty = threadIdx.x >> 5;
    int cb0 = blockIdx.y * 32, nb0 = blockIdx.x * 32;
#pragma unroll
    for (int j = 0; j < 4; j++)
        t[ty + j * 8][tx] = src[(size_t)(cb0 + ty + j * 8) * NSEQ + nb0 + tx];
    __syncthreads();
#pragma unroll
    for (int j = 0; j < 4; j++)
        dst[(size_t)(nb0 + ty + j * 8) * DMODEL + cb0 + tx] =
            __float2bfloat16_rn(t[tx][ty + j * 8]);
}

// ---------------- bf16 GEMM: 64x128 tile, BK=128, 2-stage double buffer -----
struct GemmDesc { const __nv_bfloat16 *W; const float *bias; const __nv_bfloat16 *X;
                  const float *R; float *Y; __nv_bfloat16 *Ytf; __nv_bfloat16 *Ybf; };
struct GemmBatch { GemmDesc g[6]; };

constexpr int BK = 128;
constexpr int ROWB = 256;                  // bytes per smem row (128 bf16)
constexpr int ASZ = 64 * ROWB;             // 16384
constexpr int BSZ = 128 * ROWB;            // 32768
constexpr int STG = ASZ + BSZ;             // 49152
constexpr int SMEM_CONV = 2 * STG;         // 98304

__global__ __launch_bounds__(256, 2) void conv_gemm(GemmBatch batch) {
    const GemmDesc gd = batch.g[blockIdx.z];
    extern __shared__ char smem[];
    const uint32_t sbase = (uint32_t)__cvta_generic_to_shared(smem);

    const int tid  = threadIdx.x;
    const int lane = tid & 31;
    const int warp = tid >> 5;
    const int gq   = lane >> 2;
    const int tg   = lane & 3;
    const int wm   = (warp >> 2) * 32;
    const int wn   = (warp & 3) * 32;
    const int bm0  = blockIdx.x * 64;
    const int bn0  = blockIdx.y * 128;

    float acc[2][4][4];
#pragma unroll
    for (int mi = 0; mi < 2; mi++)
#pragma unroll
        for (int ni = 0; ni < 4; ni++)
#pragma unroll
            for (int r = 0; r < 4; r++) acc[mi][ni][r] = 0.f;

    const int lj = lane >> 3;
    const int lr = lane & 7;
    uint32_t aoff[2];
#pragma unroll
    for (int mi = 0; mi < 2; mi++)
        aoff[mi] = (uint32_t)(wm + mi * 16 + (lj & 1) * 8 + lr) * ROWB;
    const int akc = lj >> 1;
    uint32_t boff[2];
#pragma unroll
    for (int g = 0; g < 2; g++)
        boff[g] = (uint32_t)(wn + g * 16 + (lj >> 1) * 8 + lr) * ROWB;
    const int bkc = lj & 1;

    auto load_stage = [&](uint32_t A, int k0) {
        uint32_t B = A + ASZ;
#pragma unroll
        for (int j = 0; j < 4; j++) {
            int idx = tid + j * 256;
            int r = idx >> 4, c = idx & 15;
            cp16(A + r * ROWB + ((c ^ (r & 7)) << 4),
                 gd.W + (size_t)(bm0 + r) * DMODEL + k0 + c * 8);
        }
#pragma unroll
        for (int j = 0; j < 8; j++) {
            int idx = tid + j * 256;
            int r = idx >> 4, c = idx & 15;
            cp16(B + r * ROWB + ((c ^ (r & 7)) << 4),
                 gd.X + (size_t)(bn0 + r) * DMODEL + k0 + c * 8);
        }
    };

    auto compute_stage = [&](uint32_t A) {
        const uint32_t B = A + ASZ;
#pragma unroll
        for (int ks = 0; ks < 8; ks++) {
            uint32_t af[2][4], bf[4][2];
#pragma unroll
            for (int mi = 0; mi < 2; mi++)
                ldsm4(af[mi][0], af[mi][1], af[mi][2], af[mi][3],
                      A + aoff[mi] + (((2 * ks + akc) ^ lr) << 4));
#pragma unroll
            for (int g = 0; g < 2; g++)
                ldsm4(bf[g * 2][0], bf[g * 2][1], bf[g * 2 + 1][0], bf[g * 2 + 1][1],
                      B + boff[g] + (((2 * ks + bkc) ^ lr) << 4));
#pragma unroll
            for (int mi = 0; mi < 2; mi++)
#pragma unroll
                for (int ni = 0; ni < 4; ni++)
                    mma_bf16(acc[mi][ni], af[mi], bf[ni][0], bf[ni][1]);
        }
    };

    load_stage(sbase, 0);
    CP_COMMIT();

#pragma unroll 2
    for (int i = 0; i < 8; i++) {
        const uint32_t Acur = sbase + (i & 1) * STG;
        const uint32_t Anxt = sbase + ((i & 1) ^ 1) * STG;
        CP_WAIT0();
        __syncthreads();

        if (i < 7) load_stage(Anxt, (i + 1) * BK);
        CP_COMMIT();

        compute_stage(Acur);
    }

#pragma unroll
    for (int mi = 0; mi < 2; mi++) {
        int row0 = bm0 + wm + mi * 16 + gq;
        int row1 = row0 + 8;
        float b0 = gd.bias[row0], b1 = gd.bias[row1];
#pragma unroll
        for (int ni = 0; ni < 4; ni++) {
            int col = bn0 + wn + ni * 8 + tg * 2;
            size_t i0 = (size_t)row0 * NSEQ + col;
            size_t i1 = (size_t)row1 * NSEQ + col;
            float v00 = acc[mi][ni][0] + b0, v01 = acc[mi][ni][1] + b0;
            float v10 = acc[mi][ni][2] + b1, v11 = acc[mi][ni][3] + b1;
            if (gd.R) {
                v00 += gd.R[i0]; v01 += gd.R[i0 + 1];
                v10 += gd.R[i1]; v11 += gd.R[i1 + 1];
            }
            if (gd.Y) {
                gd.Y[i0] = v00; gd.Y[i0 + 1] = v01;
                gd.Y[i1] = v10; gd.Y[i1 + 1] = v11;
            }
            if (gd.Ybf) {
                *(__nv_bfloat162*)&gd.Ybf[i0] = bf2(v00, v01);
                *(__nv_bfloat162*)&gd.Ybf[i1] = bf2(v10, v11);
            }
            if (gd.Ytf) {
                gd.Ytf[(size_t)(col + 0) * DMODEL + row0] = __float2bfloat16_rn(v00);
                gd.Ytf[(size_t)(col + 1) * DMODEL + row0] = __float2bfloat16_rn(v01);
                gd.Ytf[(size_t)(col + 0) * DMODEL + row1] = __float2bfloat16_rn(v10);
                gd.Ytf[(size_t)(col + 1) * DMODEL + row1] = __float2bfloat16_rn(v11);
            }
        }
    }
}

// ---------------- bf16 flash attention: split-KV (2 x 512), 4 CTAs/SM -------
#define QSCALE (0.125f * 1.4426950408889634f)   // 1/sqrt(64) * log2(e)
constexpr int HC = 512;                          // columns per KV pass
constexpr int SMEM_FLASH = 32768;                // Ks2 16KB + Vs 16KB

__global__ __launch_bounds__(256, 4) void flash_kernel(const __nv_bfloat16* __restrict__ Qb,
                                                       const __nv_bfloat16* __restrict__ Kb,
                                                       const __nv_bfloat16* __restrict__ Vb,
                                                       __nv_bfloat16* __restrict__ XTb) {
    extern __shared__ uint32_t fsm[];
    uint32_t* Ks2 = fsm;             // [8][512] words; 16B-chunk swizzle ^((h2&3)<<1)
    uint32_t* Vs  = fsm + 8 * 512;   // [16][256] words; 16B-chunk swizzle ^(h&7)
    const uint32_t ksbase = (uint32_t)__cvta_generic_to_shared(Ks2);
    const uint32_t vsbase = (uint32_t)__cvta_generic_to_shared(Vs);

    const int item = blockIdx.z;
    const int d    = blockIdx.x;
    const int nb   = blockIdx.y * 256;
    const int tid  = threadIdx.x;
    const int warp = tid >> 5;
    const int lane = tid & 31;
    const int gq   = lane >> 2;
    const int tg   = lane & 3;

    const __nv_bfloat16* Qg = Qb + (size_t)item * MN + (size_t)(d * 16) * NSEQ;
    const __nv_bfloat16* Kg = Kb + (size_t)item * MN + (size_t)(d * 16) * NSEQ;
    const __nv_bfloat16* Vg = Vb + (size_t)item * MN + (size_t)(d * 16) * NSEQ;
    __nv_bfloat16* XT = XTb + (size_t)item * MN;

    // Q A-fragments (m16n8k16, k = 16 heads), QSCALE folded
    uint32_t qf[2][4];
#pragma unroll
    for (int mt = 0; mt < 2; mt++) {
        int n0 = nb + warp * 32 + mt * 16 + gq;
        int h0 = 2 * tg;
#pragma unroll
        for (int kb = 0; kb < 2; kb++) {
            int h = h0 + kb * 8;
            float a0 = __bfloat162float(Qg[(size_t)h * NSEQ + n0]) * QSCALE;
            float a1 = __bfloat162float(Qg[(size_t)(h + 1) * NSEQ + n0]) * QSCALE;
            float b0 = __bfloat162float(Qg[(size_t)h * NSEQ + n0 + 8]) * QSCALE;
            float b1 = __bfloat162float(Qg[(size_t)(h + 1) * NSEQ + n0 + 8]) * QSCALE;
            qf[mt][kb * 2 + 0] = packbf(a0, a1);
            qf[mt][kb * 2 + 1] = packbf(b0, b1);
        }
    }

    float xacc[2][2][4];
#pragma unroll
    for (int mt = 0; mt < 2; mt++)
#pragma unroll
        for (int ht = 0; ht < 2; ht++)
#pragma unroll
            for (int r = 0; r < 4; r++) xacc[mt][ht][r] = 0.f;
    float l[4] = {0.f, 0.f, 0.f, 0.f};

    // hoisted byte-address row bases (invariant across the whole kernel)
    const uint32_t kR0 = ksbase + (tg * 512) * 4 + (gq & 3) * 4;        // row tg, word gq&3
    const uint32_t kR1 = ksbase + ((tg + 4) * 512) * 4 + (gq & 3) * 4;
    const uint32_t vR0 = vsbase + (gq * 256) * 4 + tg * 4;              // row gq, word tg
    const uint32_t vR1 = vsbase + ((8 + gq) * 256) * 4 + tg * 4;
    const int ksw = tg << 1;        // K chunk XOR
    const int g2  = gq >> 2;        // K chunk bit0
    const int vsw = gq & 7;         // V chunk XOR

#pragma unroll 1
    for (int half = 0; half < 2; half++) {
        // ---- K fill: 1024 16B-chunks (h-paired via byte_perm)
#pragma unroll
        for (int j = 0; j < 4; j++) {
            int idx = tid + j * 256;
            int h2 = idx >> 7;
            int mc = idx & 127;
            int m = half * HC + mc * 4;
            uint2 uA = *(const uint2*)(Kg + (size_t)(2 * h2) * NSEQ + m);
            uint2 uB = *(const uint2*)(Kg + (size_t)(2 * h2 + 1) * NSEQ + m);
            uint4 o;
            o.x = __byte_perm(uA.x, uB.x, 0x5410);
            o.y = __byte_perm(uA.x, uB.x, 0x7632);
            o.z = __byte_perm(uA.y, uB.y, 0x5410);
            o.w = __byte_perm(uA.y, uB.y, 0x7632);
            *(uint4*)(Ks2 + h2 * 512 + ((mc ^ ((h2 & 3) << 1)) << 2)) = o;
        }
        // ---- V fill: 1024 16B-chunks, straight copy
#pragma unroll
        for (int j = 0; j < 4; j++) {
            int idx = tid + j * 256;
            int h = idx >> 6;
            int mc = idx & 63;
            int m = half * HC + mc * 8;
            uint4 v = *(const uint4*)(Vg + (size_t)h * NSEQ + m);
            *(uint4*)(Vs + h * 256 + ((mc ^ (h & 7)) << 2)) = v;
        }
        __syncthreads();

#pragma unroll 2
        for (int m0 = 0; m0 < HC; m0 += 16) {
            // K chunk byte-offset = chunk<<4 ; chunk = ((m0>>2)|g2)^ksw
            int kc0 = ((((m0) >> 2) | g2) ^ ksw) << 4;
            int kc1 = ((((m0 + 8) >> 2) | g2) ^ ksw) << 4;
            uint32_t kb00, kb01, kb10, kb11;
            asm volatile("ld.shared.b32 %0, [%1];" : "=r"(kb00) : "r"(kR0 + kc0));
            asm volatile("ld.shared.b32 %0, [%1];" : "=r"(kb01) : "r"(kR1 + kc0));
            asm volatile("ld.shared.b32 %0, [%1];" : "=r"(kb10) : "r"(kR0 + kc1));
            asm volatile("ld.shared.b32 %0, [%1];" : "=r"(kb11) : "r"(kR1 + kc1));

            int c0 = m0 >> 3;
            int vc0 = ((c0 ^ vsw) << 4);
            int vc1 = (((c0 + 1) ^ vsw) << 4);
            uint32_t vb00, vb01, vb10, vb11;
            asm volatile("ld.shared.b32 %0, [%1];" : "=r"(vb00) : "r"(vR0 + vc0));
            asm volatile("ld.shared.b32 %0, [%1];" : "=r"(vb01) : "r"(vR0 + vc1));
            asm volatile("ld.shared.b32 %0, [%1];" : "=r"(vb10) : "r"(vR1 + vc0));
            asm volatile("ld.shared.b32 %0, [%1];" : "=r"(vb11) : "r"(vR1 + vc1));

#pragma unroll
            for (int mt = 0; mt < 2; mt++) {
                float s0[4] = {0.f, 0.f, 0.f, 0.f};
                float s1[4] = {0.f, 0.f, 0.f, 0.f};
                mma_bf16(s0, qf[mt], kb00, kb01);
                mma_bf16(s1, qf[mt], kb10, kb11);

                float p00 = ex2f(s0[0]), p01 = ex2f(s0[1]);
                float p02 = ex2f(s0[2]), p03 = ex2f(s0[3]);
                float p10 = ex2f(s1[0]), p11 = ex2f(s1[1]);
                float p12 = ex2f(s1[2]), p13 = ex2f(s1[3]);
                l[mt * 2 + 0] += (p00 + p01) + (p10 + p11);
                l[mt * 2 + 1] += (p02 + p03) + (p12 + p13);

                uint32_t pa[4];
                pa[0] = packbf(p00, p01);
                pa[1] = packbf(p02, p03);
                pa[2] = packbf(p10, p11);
                pa[3] = packbf(p12, p13);

                mma_bf16(xacc[mt][0], pa, vb00, vb01);
                mma_bf16(xacc[mt][1], pa, vb10, vb11);
            }
        }
        __syncthreads();
    }

#pragma unroll
    for (int i = 0; i < 4; i++) {
        l[i] += __shfl_xor_sync(0xffffffffu, l[i], 1);
        l[i] += __shfl_xor_sync(0xffffffffu, l[i], 2);
    }
#pragma unroll
    for (int mt = 0; mt < 2; mt++) {
        float inv0 = 1.0f / l[mt * 2 + 0];
        float inv1 = 1.0f / l[mt * 2 + 1];
        int n0 = nb + warp * 32 + mt * 16 + gq;
#pragma unroll
        for (int ht = 0; ht < 2; ht++) {
            int h = d * 16 + ht * 8 + 2 * tg;
            *(__nv_bfloat162*)&XT[(size_t)n0 * DMODEL + h] =
                bf2(xacc[mt][ht][0] * inv0, xacc[mt][ht][1] * inv0);
            *(__nv_bfloat162*)&XT[(size_t)(n0 + 8) * DMODEL + h] =
                bf2(xacc[mt][ht][2] * inv1, xacc[mt][ht][3] * inv1);
        }
    }
}

// ---------------- launch ----------------
extern "C" void kernel_launch(void* const* d_in, const int* in_sizes, int n_in,
                              void* d_out, int out_size) {
    (void)in_sizes; (void)n_in; (void)out_size;

    const float* desc0 = (const float*)d_in[0];
    const float* desc1 = (const float*)d_in[1];
    const float* Wq = (const float*)d_in[2]; const float* bq = (const float*)d_in[3];
    const float* Wk = (const float*)d_in[4]; const float* bk = (const float*)d_in[5];
    const float* Wv = (const float*)d_in[6]; const float* bv = (const float*)d_in[7];
    const float* Wm = (const float*)d_in[8]; const float* bm = (const float*)d_in[9];

    float* out0 = (float*)d_out;
    float* out1 = out0 + MN;

    __nv_bfloat16 *Qb, *Kb, *Vb, *Xb, *Wt, *Dt, *Tt;
    cudaGetSymbolAddress((void**)&Qb, g_Q);
    cudaGetSymbolAddress((void**)&Kb, g_K);
    cudaGetSymbolAddress((void**)&Vb, g_V);
    cudaGetSymbolAddress((void**)&Xb, g_X);
    cudaGetSymbolAddress((void**)&Wt, g_W);
    cudaGetSymbolAddress((void**)&Dt, g_D);
    cudaGetSymbolAddress((void**)&Tt, g_T);

    __nv_bfloat16* W0 = Wt;           __nv_bfloat16* W1 = Wt + MN;
    __nv_bfloat16* W2 = Wt + 2 * MN;  __nv_bfloat16* W3 = Wt + 3 * MN;
    __nv_bfloat16* D0 = Dt;           __nv_bfloat16* D1 = Dt + MN;
    __nv_bfloat16* T0 = Tt;           __nv_bfloat16* T1 = Tt + MN;

    cudaFuncSetAttribute(conv_gemm, cudaFuncAttributeMaxDynamicSharedMemorySize, SMEM_CONV);
    cudaFuncSetAttribute(conv_gemm, cudaFuncAttributePreferredSharedMemoryCarveout,
                         cudaSharedmemCarveoutMaxShared);
    cudaFuncSetAttribute(flash_kernel, cudaFuncAttributeMaxDynamicSharedMemorySize, SMEM_FLASH);
    cudaFuncSetAttribute(flash_kernel, cudaFuncAttributePreferredSharedMemoryCarveout,
                         cudaSharedmemCarveoutMaxShared);

    // ---- prep
    CvtBatch cb{};
    cb.s[0] = Wq; cb.d[0] = W0;
    cb.s[1] = Wk; cb.d[1] = W1;
    cb.s[2] = Wv; cb.d[2] = W2;
    cb.s[3] = Wm; cb.d[3] = W3;
    prep_round<<<dim3(1024, 4), 256>>>(cb);
    CvtTBatch ct{};
    ct.s[0] = desc0; ct.d[0] = D0;
    ct.s[1] = desc1; ct.d[1] = D1;
    prep_round_T<<<dim3(32, 32, 2), 256>>>(ct);

    // ---- attn1 (desc0 self) + attn2 (desc1 self): QKV GEMMs -> bf16 direct
    GemmBatch A{};
    A.g[0] = {W0, bq, D0, nullptr, nullptr, nullptr, Qb};
    A.g[1] = {W1, bk, D0, nullptr, nullptr, nullptr, Kb};
    A.g[2] = {W2, bv, D0, nullptr, nullptr, nullptr, Vb};
    A.g[3] = {W0, bq, D1, nullptr, nullptr, nullptr, Qb + MN};
    A.g[4] = {W1, bk, D1, nullptr, nullptr, nullptr, Kb + MN};
    A.g[5] = {W2, bv, D1, nullptr, nullptr, nullptr, Vb + MN};
    conv_gemm<<<dim3(16, 8, 6), 256, SMEM_CONV>>>(A);

    flash_kernel<<<dim3(64, 4, 2), 256, SMEM_FLASH>>>(Qb, Kb, Vb, Xb);

    // d0 = desc0 + Wm@X0 + bm ; d1 = desc1 + Wm@X1 + bm
    GemmBatch C{};
    C.g[0] = {W3, bm, Xb,      desc0, out0, T0, nullptr};
    C.g[1] = {W3, bm, Xb + MN, desc1, out1, T1, nullptr};
    conv_gemm<<<dim3(16, 8, 2), 256, SMEM_CONV>>>(C);

    // ---- attn3: q=d0, kv=d1
    GemmBatch Dq{};
    Dq.g[0] = {W0, bq, T0, nullptr, nullptr, nullptr, Qb};
    Dq.g[1] = {W1, bk, T1, nullptr, nullptr, nullptr, Kb};
    Dq.g[2] = {W2, bv, T1, nullptr, nullptr, nullptr, Vb};
    conv_gemm<<<dim3(16, 8, 3), 256, SMEM_CONV>>>(Dq);

    flash_kernel<<<dim3(64, 4, 1), 256, SMEM_FLASH>>>(Qb, Kb, Vb, Xb);

    // ---- F (d0 += conv(x), refresh T0) merged with attn4's Q GEMM (needs only T1)
    GemmBatch FG{};
    FG.g[0] = {W3, bm, Xb, out0, out0, T0, nullptr};
    FG.g[1] = {W0, bq, T1, nullptr, nullptr, nullptr, Qb};
    conv_gemm<<<dim3(16, 8, 2), 256, SMEM_CONV>>>(FG);

    // ---- attn4 K,V GEMMs (need T0 from F)
    GemmBatch G{};
    G.g[0] = {W1, bk, T0, nullptr, nullptr, nullptr, Kb};
    G.g[1] = {W2, bv, T0, nullptr, nullptr, nullptr, Vb};
    conv_gemm<<<dim3(16, 8, 2), 256, SMEM_CONV>>>(G);

    flash_kernel<<<dim3(64, 4, 1), 256, SMEM_FLASH>>>(Qb, Kb, Vb, Xb);

    GemmBatch I{};
    I.g[0] = {W3, bm, Xb, out1, out1, nullptr, nullptr};
    conv_gemm<<<dim3(16, 8, 1), 256, SMEM_CONV>>>(I);
}

// round 15
// speedup vs baseline: 1.0535x; 1.0535x over previous
#include <cuda_runtime.h>
#include <cuda_bf16.h>
#include <cstdint>

#define DMODEL 1024
#define NSEQ   1024
static const int MN = DMODEL * NSEQ;

// ---------------- scratch (device globals; no allocs allowed) ----------------
__device__ __nv_bfloat16 g_Q[2 * 1024 * 1024];   // Q [c][n] bf16
__device__ __nv_bfloat16 g_K[2 * 1024 * 1024];   // K [c][n] bf16
__device__ __nv_bfloat16 g_V[2 * 1024 * 1024];   // V [c][n] bf16
__device__ __nv_bfloat16 g_X[2 * 1024 * 1024];   // X^T per item: [n][c] bf16
__device__ __nv_bfloat16 g_W[4 * 1024 * 1024];   // weights bf16 [m][k]
__device__ __nv_bfloat16 g_D[2 * 1024 * 1024];   // desc^T bf16 [n][c]
__device__ __nv_bfloat16 g_T[2 * 1024 * 1024];   // out^T bf16 mirrors [n][c]

__device__ __forceinline__ float ex2f(float x) {
    float y;
    asm("ex2.approx.f32 %0, %1;" : "=f"(y) : "f"(x));
    return y;
}
__device__ __forceinline__ void mma_bf16(float* d, const uint32_t* a, uint32_t b0, uint32_t b1) {
    asm volatile(
        "mma.sync.aligned.m16n8k16.row.col.f32.bf16.bf16.f32 "
        "{%0,%1,%2,%3}, {%4,%5,%6,%7}, {%8,%9}, {%0,%1,%2,%3};"
        : "+f"(d[0]), "+f"(d[1]), "+f"(d[2]), "+f"(d[3])
        : "r"(a[0]), "r"(a[1]), "r"(a[2]), "r"(a[3]), "r"(b0), "r"(b1));
}
__device__ __forceinline__ void ldsm4(uint32_t& r0, uint32_t& r1, uint32_t& r2, uint32_t& r3,
                                      uint32_t addr) {
    asm volatile("ldmatrix.sync.aligned.m8n8.x4.shared.b16 {%0,%1,%2,%3}, [%4];"
                 : "=r"(r0), "=r"(r1), "=r"(r2), "=r"(r3) : "r"(addr));
}
__device__ __forceinline__ void cp16(uint32_t dst, const void* src) {
    asm volatile("cp.async.cg.shared.global [%0], [%1], 16;" :: "r"(dst), "l"(src));
}
#define CP_COMMIT() asm volatile("cp.async.commit_group;")
#define CP_WAIT0()  asm volatile("cp.async.wait_group 0;")

__device__ __forceinline__ __nv_bfloat162 bf2(float lo, float hi) {
    __nv_bfloat162 t;
    t.x = __float2bfloat16_rn(lo);
    t.y = __float2bfloat16_rn(hi);
    return t;
}
__device__ __forceinline__ uint32_t packbf(float lo, float hi) {
    uint32_t r;
    asm("cvt.rn.bf16x2.f32 %0, %1, %2;" : "=r"(r) : "f"(hi), "f"(lo));
    return r;
}

// ---------------- prep: bf16-round weights; transpose+round descs ------------
struct CvtBatch { const float* s[4]; __nv_bfloat16* d[4]; };

__global__ __launch_bounds__(256) void prep_round(CvtBatch cb) {
    const float4* s = (const float4*)cb.s[blockIdx.y];
    __nv_bfloat162* d = (__nv_bfloat162*)cb.d[blockIdx.y];
    int i = blockIdx.x * 256 + threadIdx.x;
    float4 v = s[i];
    d[2 * i]     = bf2(v.x, v.y);
    d[2 * i + 1] = bf2(v.z, v.w);
}

struct CvtTBatch { const float* s[2]; __nv_bfloat16* d[2]; };

// dst[n][c] = bf16(src[c][n])
__global__ __launch_bounds__(256) void prep_round_T(CvtTBatch cb) {
    __shared__ float t[32][33];
    const float* src = cb.s[blockIdx.z];
    __nv_bfloat16* dst = cb.d[blockIdx.z];
    int tx = threadIdx.x & 31, ty = threadIdx.x >> 5;
    int cb0 = blockIdx.y * 32, nb0 = blockIdx.x * 32;
#pragma unroll
    for (int j = 0; j < 4; j++)
        t[ty + j * 8][tx] = src[(size_t)(cb0 + ty + j * 8) * NSEQ + nb0 + tx];
    __syncthreads();
#pragma unroll
    for (int j = 0; j < 4; j++)
        dst[(size_t)(nb0 + ty + j * 8) * DMODEL + cb0 + tx] =
            __float2bfloat16_rn(t[tx][ty + j * 8]);
}

// ---------------- bf16 GEMM: 128x128 tile, BK=64, 2-stage double buffer -----
// Y[m,n] = sum_k W[m,k] * Bt[n,k] + bias[m] (+R).  grid (8, 8, z).
// Stage: A 16KB + B 16KB = 32KB; 2 stages = 64KB; 2 CTAs/SM.

struct GemmDesc { const __nv_bfloat16 *W; const float *bias; const __nv_bfloat16 *X;
                  const float *R; float *Y; __nv_bfloat16 *Ytf; __nv_bfloat16 *Ybf; };
struct GemmBatch { GemmDesc g[6]; };

constexpr int BK = 64;
constexpr int ROWB = 128;                  // bytes per smem row (64 bf16)
constexpr int ASZ = 128 * ROWB;            // 16384
constexpr int BSZ = 128 * ROWB;            // 16384
constexpr int STG = ASZ + BSZ;             // 32768
constexpr int SMEM_CONV = 2 * STG;         // 65536

__global__ __launch_bounds__(256, 2) void conv_gemm(GemmBatch batch) {
    const GemmDesc gd = batch.g[blockIdx.z];
    extern __shared__ char smem[];
    const uint32_t sbase = (uint32_t)__cvta_generic_to_shared(smem);

    const int tid  = threadIdx.x;
    const int lane = tid & 31;
    const int warp = tid >> 5;
    const int gq   = lane >> 2;
    const int tg   = lane & 3;
    const int wm   = (warp >> 2) * 64;     // 4 m-tiles of 16 per warp
    const int wn   = (warp & 3) * 32;
    const int bm0  = blockIdx.x * 128;
    const int bn0  = blockIdx.y * 128;

    float acc[4][4][4];
#pragma unroll
    for (int mi = 0; mi < 4; mi++)
#pragma unroll
        for (int ni = 0; ni < 4; ni++)
#pragma unroll
            for (int r = 0; r < 4; r++) acc[mi][ni][r] = 0.f;

    const int lj = lane >> 3;
    const int lr = lane & 7;
    uint32_t aoff[4];
#pragma unroll
    for (int mi = 0; mi < 4; mi++)
        aoff[mi] = (uint32_t)(wm + mi * 16 + (lj & 1) * 8 + lr) * ROWB;
    const int akc = lj >> 1;
    uint32_t boff[2];
#pragma unroll
    for (int g = 0; g < 2; g++)
        boff[g] = (uint32_t)(wn + g * 16 + (lj >> 1) * 8 + lr) * ROWB;
    const int bkc = lj & 1;

    // stage loader: 128 rows x 8 chunks (16B = 8 bf16) for A and B
    auto load_stage = [&](int stg, int k0) {
        uint32_t A = sbase + stg * STG;
        uint32_t B = A + ASZ;
#pragma unroll
        for (int j = 0; j < 4; j++) {
            int idx = tid + j * 256;
            int r = idx >> 3, c = idx & 7;
            cp16(A + r * ROWB + ((c ^ (r & 7)) << 4),
                 gd.W + (size_t)(bm0 + r) * DMODEL + k0 + c * 8);
        }
#pragma unroll
        for (int j = 0; j < 4; j++) {
            int idx = tid + j * 256;
            int r = idx >> 3, c = idx & 7;
            cp16(B + r * ROWB + ((c ^ (r & 7)) << 4),
                 gd.X + (size_t)(bn0 + r) * DMODEL + k0 + c * 8);
        }
    };

    load_stage(0, 0);
    CP_COMMIT();

#pragma unroll 1
    for (int i = 0; i < 16; i++) {
        const int s = i & 1;
        CP_WAIT0();
        __syncthreads();

        if (i < 15) load_stage(s ^ 1, (i + 1) * BK);
        CP_COMMIT();

        const uint32_t A = sbase + s * STG;
        const uint32_t B = A + ASZ;
#pragma unroll
        for (int ks = 0; ks < 4; ks++) {           // 4 k16-steps of BK=64
            uint32_t af[4][4], bf[4][2];
#pragma unroll
            for (int mi = 0; mi < 4; mi++)
                ldsm4(af[mi][0], af[mi][1], af[mi][2], af[mi][3],
                      A + aoff[mi] + (((2 * ks + akc) ^ lr) << 4));
#pragma unroll
            for (int g = 0; g < 2; g++)
                ldsm4(bf[g * 2][0], bf[g * 2][1], bf[g * 2 + 1][0], bf[g * 2 + 1][1],
                      B + boff[g] + (((2 * ks + bkc) ^ lr) << 4));
#pragma unroll
            for (int mi = 0; mi < 4; mi++)
#pragma unroll
                for (int ni = 0; ni < 4; ni++)
                    mma_bf16(acc[mi][ni], af[mi], bf[ni][0], bf[ni][1]);
        }
    }

#pragma unroll
    for (int mi = 0; mi < 4; mi++) {
        int row0 = bm0 + wm + mi * 16 + gq;
        int row1 = row0 + 8;
        float b0 = gd.bias[row0], b1 = gd.bias[row1];
#pragma unroll
        for (int ni = 0; ni < 4; ni++) {
            int col = bn0 + wn + ni * 8 + tg * 2;
            size_t i0 = (size_t)row0 * NSEQ + col;
            size_t i1 = (size_t)row1 * NSEQ + col;
            float v00 = acc[mi][ni][0] + b0, v01 = acc[mi][ni][1] + b0;
            float v10 = acc[mi][ni][2] + b1, v11 = acc[mi][ni][3] + b1;
            if (gd.R) {
                v00 += gd.R[i0]; v01 += gd.R[i0 + 1];
                v10 += gd.R[i1]; v11 += gd.R[i1 + 1];
            }
            if (gd.Y) {
                gd.Y[i0] = v00; gd.Y[i0 + 1] = v01;
                gd.Y[i1] = v10; gd.Y[i1 + 1] = v11;
            }
            if (gd.Ybf) {
                *(__nv_bfloat162*)&gd.Ybf[i0] = bf2(v00, v01);
                *(__nv_bfloat162*)&gd.Ybf[i1] = bf2(v10, v11);
            }
            if (gd.Ytf) {
                gd.Ytf[(size_t)(col + 0) * DMODEL + row0] = __float2bfloat16_rn(v00);
                gd.Ytf[(size_t)(col + 1) * DMODEL + row0] = __float2bfloat16_rn(v01);
                gd.Ytf[(size_t)(col + 0) * DMODEL + row1] = __float2bfloat16_rn(v10);
                gd.Ytf[(size_t)(col + 1) * DMODEL + row1] = __float2bfloat16_rn(v11);
            }
        }
    }
}

// ---------------- bf16 flash attention: split-KV (2 x 512), 4 CTAs/SM -------
#define QSCALE (0.125f * 1.4426950408889634f)   // 1/sqrt(64) * log2(e)
constexpr int HC = 512;                          // columns per KV pass
constexpr int SMEM_FLASH = 32768;                // Ks2 16KB + Vs 16KB

__global__ __launch_bounds__(256, 4) void flash_kernel(const __nv_bfloat16* __restrict__ Qb,
                                                       const __nv_bfloat16* __restrict__ Kb,
                                                       const __nv_bfloat16* __restrict__ Vb,
                                                       __nv_bfloat16* __restrict__ XTb) {
    extern __shared__ uint32_t fsm[];
    uint32_t* Ks2 = fsm;             // [8][512] words; 16B-chunk swizzle ^((h2&3)<<1)
    uint32_t* Vs  = fsm + 8 * 512;   // [16][256] words; 16B-chunk swizzle ^(h&7)
    const uint32_t ksbase = (uint32_t)__cvta_generic_to_shared(Ks2);
    const uint32_t vsbase = (uint32_t)__cvta_generic_to_shared(Vs);

    const int item = blockIdx.z;
    const int d    = blockIdx.x;
    const int nb   = blockIdx.y * 256;
    const int tid  = threadIdx.x;
    const int warp = tid >> 5;
    const int lane = tid & 31;
    const int gq   = lane >> 2;
    const int tg   = lane & 3;

    const __nv_bfloat16* Qg = Qb + (size_t)item * MN + (size_t)(d * 16) * NSEQ;
    const __nv_bfloat16* Kg = Kb + (size_t)item * MN + (size_t)(d * 16) * NSEQ;
    const __nv_bfloat16* Vg = Vb + (size_t)item * MN + (size_t)(d * 16) * NSEQ;
    __nv_bfloat16* XT = XTb + (size_t)item * MN;

    // Q A-fragments (m16n8k16, k = 16 heads), QSCALE folded
    uint32_t qf[2][4];
#pragma unroll
    for (int mt = 0; mt < 2; mt++) {
        int n0 = nb + warp * 32 + mt * 16 + gq;
        int h0 = 2 * tg;
#pragma unroll
        for (int kb = 0; kb < 2; kb++) {
            int h = h0 + kb * 8;
            float a0 = __bfloat162float(Qg[(size_t)h * NSEQ + n0]) * QSCALE;
            float a1 = __bfloat162float(Qg[(size_t)(h + 1) * NSEQ + n0]) * QSCALE;
            float b0 = __bfloat162float(Qg[(size_t)h * NSEQ + n0 + 8]) * QSCALE;
            float b1 = __bfloat162float(Qg[(size_t)(h + 1) * NSEQ + n0 + 8]) * QSCALE;
            qf[mt][kb * 2 + 0] = packbf(a0, a1);
            qf[mt][kb * 2 + 1] = packbf(b0, b1);
        }
    }

    float xacc[2][2][4];
#pragma unroll
    for (int mt = 0; mt < 2; mt++)
#pragma unroll
        for (int ht = 0; ht < 2; ht++)
#pragma unroll
            for (int r = 0; r < 4; r++) xacc[mt][ht][r] = 0.f;
    float l[4] = {0.f, 0.f, 0.f, 0.f};

    // hoisted byte-address row bases (invariant across the whole kernel)
    const uint32_t kR0 = ksbase + (tg * 512) * 4 + (gq & 3) * 4;
    const uint32_t kR1 = ksbase + ((tg + 4) * 512) * 4 + (gq & 3) * 4;
    const uint32_t vR0 = vsbase + (gq * 256) * 4 + tg * 4;
    const uint32_t vR1 = vsbase + ((8 + gq) * 256) * 4 + tg * 4;
    const int ksw = tg << 1;
    const int g2  = gq >> 2;
    const int vsw = gq & 7;

#pragma unroll 1
    for (int half = 0; half < 2; half++) {
        // ---- K fill: 1024 16B-chunks (h-paired via byte_perm)
#pragma unroll
        for (int j = 0; j < 4; j++) {
            int idx = tid + j * 256;
            int h2 = idx >> 7;
            int mc = idx & 127;
            int m = half * HC + mc * 4;
            uint2 uA = *(const uint2*)(Kg + (size_t)(2 * h2) * NSEQ + m);
            uint2 uB = *(const uint2*)(Kg + (size_t)(2 * h2 + 1) * NSEQ + m);
            uint4 o;
            o.x = __byte_perm(uA.x, uB.x, 0x5410);
            o.y = __byte_perm(uA.x, uB.x, 0x7632);
            o.z = __byte_perm(uA.y, uB.y, 0x5410);
            o.w = __byte_perm(uA.y, uB.y, 0x7632);
            *(uint4*)(Ks2 + h2 * 512 + ((mc ^ ((h2 & 3) << 1)) << 2)) = o;
        }
        // ---- V fill: 1024 16B-chunks, straight copy
#pragma unroll
        for (int j = 0; j < 4; j++) {
            int idx = tid + j * 256;
            int h = idx >> 6;
            int mc = idx & 63;
            int m = half * HC + mc * 8;
            uint4 v = *(const uint4*)(Vg + (size_t)h * NSEQ + m);
            *(uint4*)(Vs + h * 256 + ((mc ^ (h & 7)) << 2)) = v;
        }
        __syncthreads();

#pragma unroll 2
        for (int m0 = 0; m0 < HC; m0 += 16) {
            int kc0 = ((((m0) >> 2) | g2) ^ ksw) << 4;
            int kc1 = ((((m0 + 8) >> 2) | g2) ^ ksw) << 4;
            uint32_t kb00, kb01, kb10, kb11;
            asm volatile("ld.shared.b32 %0, [%1];" : "=r"(kb00) : "r"(kR0 + kc0));
            asm volatile("ld.shared.b32 %0, [%1];" : "=r"(kb01) : "r"(kR1 + kc0));
            asm volatile("ld.shared.b32 %0, [%1];" : "=r"(kb10) : "r"(kR0 + kc1));
            asm volatile("ld.shared.b32 %0, [%1];" : "=r"(kb11) : "r"(kR1 + kc1));

            int c0 = m0 >> 3;
            int vc0 = ((c0 ^ vsw) << 4);
            int vc1 = (((c0 + 1) ^ vsw) << 4);
            uint32_t vb00, vb01, vb10, vb11;
            asm volatile("ld.shared.b32 %0, [%1];" : "=r"(vb00) : "r"(vR0 + vc0));
            asm volatile("ld.shared.b32 %0, [%1];" : "=r"(vb01) : "r"(vR0 + vc1));
            asm volatile("ld.shared.b32 %0, [%1];" : "=r"(vb10) : "r"(vR1 + vc0));
            asm volatile("ld.shared.b32 %0, [%1];" : "=r"(vb11) : "r"(vR1 + vc1));

#pragma unroll
            for (int mt = 0; mt < 2; mt++) {
                float s0[4] = {0.f, 0.f, 0.f, 0.f};
                float s1[4] = {0.f, 0.f, 0.f, 0.f};
                mma_bf16(s0, qf[mt], kb00, kb01);
                mma_bf16(s1, qf[mt], kb10, kb11);

                float p00 = ex2f(s0[0]), p01 = ex2f(s0[1]);
                float p02 = ex2f(s0[2]), p03 = ex2f(s0[3]);
                float p10 = ex2f(s1[0]), p11 = ex2f(s1[1]);
                float p12 = ex2f(s1[2]), p13 = ex2f(s1[3]);
                l[mt * 2 + 0] += (p00 + p01) + (p10 + p11);
                l[mt * 2 + 1] += (p02 + p03) + (p12 + p13);

                uint32_t pa[4];
                pa[0] = packbf(p00, p01);
                pa[1] = packbf(p02, p03);
                pa[2] = packbf(p10, p11);
                pa[3] = packbf(p12, p13);

                mma_bf16(xacc[mt][0], pa, vb00, vb01);
                mma_bf16(xacc[mt][1], pa, vb10, vb11);
            }
        }
        __syncthreads();
    }

#pragma unroll
    for (int i = 0; i < 4; i++) {
        l[i] += __shfl_xor_sync(0xffffffffu, l[i], 1);
        l[i] += __shfl_xor_sync(0xffffffffu, l[i], 2);
    }
#pragma unroll
    for (int mt = 0; mt < 2; mt++) {
        float inv0 = 1.0f / l[mt * 2 + 0];
        float inv1 = 1.0f / l[mt * 2 + 1];
        int n0 = nb + warp * 32 + mt * 16 + gq;
#pragma unroll
        for (int ht = 0; ht < 2; ht++) {
            int h = d * 16 + ht * 8 + 2 * tg;
            *(__nv_bfloat162*)&XT[(size_t)n0 * DMODEL + h] =
                bf2(xacc[mt][ht][0] * inv0, xacc[mt][ht][1] * inv0);
            *(__nv_bfloat162*)&XT[(size_t)(n0 + 8) * DMODEL + h] =
                bf2(xacc[mt][ht][2] * inv1, xacc[mt][ht][3] * inv1);
        }
    }
}

// ---------------- launch ----------------
extern "C" void kernel_launch(void* const* d_in, const int* in_sizes, int n_in,
                              void* d_out, int out_size) {
    (void)in_sizes; (void)n_in; (void)out_size;

    const float* desc0 = (const float*)d_in[0];
    const float* desc1 = (const float*)d_in[1];
    const float* Wq = (const float*)d_in[2]; const float* bq = (const float*)d_in[3];
    const float* Wk = (const float*)d_in[4]; const float* bk = (const float*)d_in[5];
    const float* Wv = (const float*)d_in[6]; const float* bv = (const float*)d_in[7];
    const float* Wm = (const float*)d_in[8]; const float* bm = (const float*)d_in[9];

    float* out0 = (float*)d_out;
    float* out1 = out0 + MN;

    __nv_bfloat16 *Qb, *Kb, *Vb, *Xb, *Wt, *Dt, *Tt;
    cudaGetSymbolAddress((void**)&Qb, g_Q);
    cudaGetSymbolAddress((void**)&Kb, g_K);
    cudaGetSymbolAddress((void**)&Vb, g_V);
    cudaGetSymbolAddress((void**)&Xb, g_X);
    cudaGetSymbolAddress((void**)&Wt, g_W);
    cudaGetSymbolAddress((void**)&Dt, g_D);
    cudaGetSymbolAddress((void**)&Tt, g_T);

    __nv_bfloat16* W0 = Wt;           __nv_bfloat16* W1 = Wt + MN;
    __nv_bfloat16* W2 = Wt + 2 * MN;  __nv_bfloat16* W3 = Wt + 3 * MN;
    __nv_bfloat16* D0 = Dt;           __nv_bfloat16* D1 = Dt + MN;
    __nv_bfloat16* T0 = Tt;           __nv_bfloat16* T1 = Tt + MN;

    cudaFuncSetAttribute(conv_gemm, cudaFuncAttributeMaxDynamicSharedMemorySize, SMEM_CONV);
    cudaFuncSetAttribute(conv_gemm, cudaFuncAttributePreferredSharedMemoryCarveout,
                         cudaSharedmemCarveoutMaxShared);
    cudaFuncSetAttribute(flash_kernel, cudaFuncAttributeMaxDynamicSharedMemorySize, SMEM_FLASH);
    cudaFuncSetAttribute(flash_kernel, cudaFuncAttributePreferredSharedMemoryCarveout,
                         cudaSharedmemCarveoutMaxShared);

    // ---- prep
    CvtBatch cb{};
    cb.s[0] = Wq; cb.d[0] = W0;
    cb.s[1] = Wk; cb.d[1] = W1;
    cb.s[2] = Wv; cb.d[2] = W2;
    cb.s[3] = Wm; cb.d[3] = W3;
    prep_round<<<dim3(1024, 4), 256>>>(cb);
    CvtTBatch ct{};
    ct.s[0] = desc0; ct.d[0] = D0;
    ct.s[1] = desc1; ct.d[1] = D1;
    prep_round_T<<<dim3(32, 32, 2), 256>>>(ct);

    // ---- attn1 (desc0 self) + attn2 (desc1 self): QKV GEMMs -> bf16 direct
    GemmBatch A{};
    A.g[0] = {W0, bq, D0, nullptr, nullptr, nullptr, Qb};
    A.g[1] = {W1, bk, D0, nullptr, nullptr, nullptr, Kb};
    A.g[2] = {W2, bv, D0, nullptr, nullptr, nullptr, Vb};
    A.g[3] = {W0, bq, D1, nullptr, nullptr, nullptr, Qb + MN};
    A.g[4] = {W1, bk, D1, nullptr, nullptr, nullptr, Kb + MN};
    A.g[5] = {W2, bv, D1, nullptr, nullptr, nullptr, Vb + MN};
    conv_gemm<<<dim3(8, 8, 6), 256, SMEM_CONV>>>(A);

    flash_kernel<<<dim3(64, 4, 2), 256, SMEM_FLASH>>>(Qb, Kb, Vb, Xb);

    // d0 = desc0 + Wm@X0 + bm ; d1 = desc1 + Wm@X1 + bm
    GemmBatch C{};
    C.g[0] = {W3, bm, Xb,      desc0, out0, T0, nullptr};
    C.g[1] = {W3, bm, Xb + MN, desc1, out1, T1, nullptr};
    conv_gemm<<<dim3(8, 8, 2), 256, SMEM_CONV>>>(C);

    // ---- attn3: q=d0, kv=d1
    GemmBatch Dq{};
    Dq.g[0] = {W0, bq, T0, nullptr, nullptr, nullptr, Qb};
    Dq.g[1] = {W1, bk, T1, nullptr, nullptr, nullptr, Kb};
    Dq.g[2] = {W2, bv, T1, nullptr, nullptr, nullptr, Vb};
    conv_gemm<<<dim3(8, 8, 3), 256, SMEM_CONV>>>(Dq);

    flash_kernel<<<dim3(64, 4, 1), 256, SMEM_FLASH>>>(Qb, Kb, Vb, Xb);

    // ---- F (d0 += conv(x), refresh T0) merged with attn4's Q GEMM (needs only T1)
    GemmBatch FG{};
    FG.g[0] = {W3, bm, Xb, out0, out0, T0, nullptr};
    FG.g[1] = {W0, bq, T1, nullptr, nullptr, nullptr, Qb};
    conv_gemm<<<dim3(8, 8, 2), 256, SMEM_CONV>>>(FG);

    // ---- attn4 K,V GEMMs (need T0 from F)
    GemmBatch G{};
    G.g[0] = {W1, bk, T0, nullptr, nullptr, nullptr, Kb};
    G.g[1] = {W2, bv, T0, nullptr, nullptr, nullptr, Vb};
    conv_gemm<<<dim3(8, 8, 2), 256, SMEM_CONV>>>(G);

    flash_kernel<<<dim3(64, 4, 1), 256, SMEM_FLASH>>>(Qb, Kb, Vb, Xb);

    GemmBatch I{};
    I.g[0] = {W3, bm, Xb, out1, out1, nullptr, nullptr};
    conv_gemm<<<dim3(8, 8, 1), 256, SMEM_CONV>>>(I);
}

// round 16
// speedup vs baseline: 1.0998x; 1.0439x over previous
#include <cuda_runtime.h>
#include <cuda_bf16.h>
#include <cstdint>

#define DMODEL 1024
#define NSEQ   1024
static const int MN = DMODEL * NSEQ;

// ---------------- scratch (device globals; no allocs allowed) ----------------
__device__ __nv_bfloat16 g_Q[2 * 1024 * 1024];   // Q [c][n] bf16
__device__ __nv_bfloat16 g_K[2 * 1024 * 1024];   // K [c][n] bf16
__device__ __nv_bfloat16 g_V[2 * 1024 * 1024];   // V [c][n] bf16
__device__ __nv_bfloat16 g_X[2 * 1024 * 1024];   // X^T per item: [n][c] bf16
__device__ __nv_bfloat16 g_W[4 * 1024 * 1024];   // weights bf16 [m][k]
__device__ __nv_bfloat16 g_D[2 * 1024 * 1024];   // desc^T bf16 [n][c]
__device__ __nv_bfloat16 g_T[2 * 1024 * 1024];   // out^T bf16 mirrors [n][c]

__device__ __forceinline__ float ex2f(float x) {
    float y;
    asm("ex2.approx.f32 %0, %1;" : "=f"(y) : "f"(x));
    return y;
}
__device__ __forceinline__ void mma_bf16(float* d, const uint32_t* a, uint32_t b0, uint32_t b1) {
    asm volatile(
        "mma.sync.aligned.m16n8k16.row.col.f32.bf16.bf16.f32 "
        "{%0,%1,%2,%3}, {%4,%5,%6,%7}, {%8,%9}, {%0,%1,%2,%3};"
        : "+f"(d[0]), "+f"(d[1]), "+f"(d[2]), "+f"(d[3])
        : "r"(a[0]), "r"(a[1]), "r"(a[2]), "r"(a[3]), "r"(b0), "r"(b1));
}
__device__ __forceinline__ void ldsm4(uint32_t& r0, uint32_t& r1, uint32_t& r2, uint32_t& r3,
                                      uint32_t addr) {
    asm volatile("ldmatrix.sync.aligned.m8n8.x4.shared.b16 {%0,%1,%2,%3}, [%4];"
                 : "=r"(r0), "=r"(r1), "=r"(r2), "=r"(r3) : "r"(addr));
}
__device__ __forceinline__ void cp16(uint32_t dst, const void* src) {
    asm volatile("cp.async.cg.shared.global [%0], [%1], 16;" :: "r"(dst), "l"(src));
}
#define CP_COMMIT() asm volatile("cp.async.commit_group;")
#define CP_WAIT0()  asm volatile("cp.async.wait_group 0;")

__device__ __forceinline__ __nv_bfloat162 bf2(float lo, float hi) {
    __nv_bfloat162 t;
    t.x = __float2bfloat16_rn(lo);
    t.y = __float2bfloat16_rn(hi);
    return t;
}
__device__ __forceinline__ uint32_t packbf(float lo, float hi) {
    uint32_t r;
    asm("cvt.rn.bf16x2.f32 %0, %1, %2;" : "=r"(r) : "f"(hi), "f"(lo));
    return r;
}

// ---------------- prep: bf16-round weights; transpose+round descs ------------
struct CvtBatch { const float* s[4]; __nv_bfloat16* d[4]; };

__global__ __launch_bounds__(256) void prep_round(CvtBatch cb) {
    const float4* s = (const float4*)cb.s[blockIdx.y];
    __nv_bfloat162* d = (__nv_bfloat162*)cb.d[blockIdx.y];
    int i = blockIdx.x * 256 + threadIdx.x;
    float4 v = s[i];
    d[2 * i]     = bf2(v.x, v.y);
    d[2 * i + 1] = bf2(v.z, v.w);
}

struct CvtTBatch { const float* s[2]; __nv_bfloat16* d[2]; };

// dst[n][c] = bf16(src[c][n])
__global__ __launch_bounds__(256) void prep_round_T(CvtTBatch cb) {
    __shared__ float t[32][33];
    const float* src = cb.s[blockIdx.z];
    __nv_bfloat16* dst = cb.d[blockIdx.z];
    int tx = threadIdx.x & 31, ty = threadIdx.x >> 5;
    int cb0 = blockIdx.y * 32, nb0 = blockIdx.x * 32;
#pragma unroll
    for (int j = 0; j < 4; j++)
        t[ty + j * 8][tx] = src[(size_t)(cb0 + ty + j * 8) * NSEQ + nb0 + tx];
    __syncthreads();
#pragma unroll
    for (int j = 0; j < 4; j++)
        dst[(size_t)(nb0 + ty + j * 8) * DMODEL + cb0 + tx] =
            __float2bfloat16_rn(t[tx][ty + j * 8]);
}

// ---------------- bf16 GEMM: 64x128 tile, BK=128, 2-stage double buffer -----
// (R12 configuration — best measured)
struct GemmDesc { const __nv_bfloat16 *W; const float *bias; const __nv_bfloat16 *X;
                  const float *R; float *Y; __nv_bfloat16 *Ytf; __nv_bfloat16 *Ybf; };
struct GemmBatch { GemmDesc g[6]; };

constexpr int BK = 128;
constexpr int ROWB = 256;                  // bytes per smem row (128 bf16)
constexpr int ASZ = 64 * ROWB;             // 16384
constexpr int BSZ = 128 * ROWB;            // 32768
constexpr int STG = ASZ + BSZ;             // 49152
constexpr int SMEM_CONV = 2 * STG;         // 98304

__global__ __launch_bounds__(256, 2) void conv_gemm(GemmBatch batch) {
    const GemmDesc gd = batch.g[blockIdx.z];
    extern __shared__ char smem[];
    const uint32_t sbase = (uint32_t)__cvta_generic_to_shared(smem);

    const int tid  = threadIdx.x;
    const int lane = tid & 31;
    const int warp = tid >> 5;
    const int gq   = lane >> 2;
    const int tg   = lane & 3;
    const int wm   = (warp >> 2) * 32;
    const int wn   = (warp & 3) * 32;
    const int bm0  = blockIdx.x * 64;
    const int bn0  = blockIdx.y * 128;

    float acc[2][4][4];
#pragma unroll
    for (int mi = 0; mi < 2; mi++)
#pragma unroll
        for (int ni = 0; ni < 4; ni++)
#pragma unroll
            for (int r = 0; r < 4; r++) acc[mi][ni][r] = 0.f;

    const int lj = lane >> 3;
    const int lr = lane & 7;
    uint32_t aoff[2];
#pragma unroll
    for (int mi = 0; mi < 2; mi++)
        aoff[mi] = (uint32_t)(wm + mi * 16 + (lj & 1) * 8 + lr) * ROWB;
    const int akc = lj >> 1;
    uint32_t boff[2];
#pragma unroll
    for (int g = 0; g < 2; g++)
        boff[g] = (uint32_t)(wn + g * 16 + (lj >> 1) * 8 + lr) * ROWB;
    const int bkc = lj & 1;

    auto load_stage = [&](int stg, int k0) {
        uint32_t A = sbase + stg * STG;
        uint32_t B = A + ASZ;
#pragma unroll
        for (int j = 0; j < 4; j++) {
            int idx = tid + j * 256;
            int r = idx >> 4, c = idx & 15;
            cp16(A + r * ROWB + ((c ^ (r & 7)) << 4),
                 gd.W + (size_t)(bm0 + r) * DMODEL + k0 + c * 8);
        }
#pragma unroll
        for (int j = 0; j < 8; j++) {
            int idx = tid + j * 256;
            int r = idx >> 4, c = idx & 15;
            cp16(B + r * ROWB + ((c ^ (r & 7)) << 4),
                 gd.X + (size_t)(bn0 + r) * DMODEL + k0 + c * 8);
        }
    };

    load_stage(0, 0);
    CP_COMMIT();

#pragma unroll 1
    for (int i = 0; i < 8; i++) {
        const int s = i & 1;
        CP_WAIT0();
        __syncthreads();

        if (i < 7) load_stage(s ^ 1, (i + 1) * BK);
        CP_COMMIT();

        const uint32_t A = sbase + s * STG;
        const uint32_t B = A + ASZ;
#pragma unroll
        for (int ks = 0; ks < 8; ks++) {
            uint32_t af[2][4], bf[4][2];
#pragma unroll
            for (int mi = 0; mi < 2; mi++)
                ldsm4(af[mi][0], af[mi][1], af[mi][2], af[mi][3],
                      A + aoff[mi] + (((2 * ks + akc) ^ lr) << 4));
#pragma unroll
            for (int g = 0; g < 2; g++)
                ldsm4(bf[g * 2][0], bf[g * 2][1], bf[g * 2 + 1][0], bf[g * 2 + 1][1],
                      B + boff[g] + (((2 * ks + bkc) ^ lr) << 4));
#pragma unroll
            for (int mi = 0; mi < 2; mi++)
#pragma unroll
                for (int ni = 0; ni < 4; ni++)
                    mma_bf16(acc[mi][ni], af[mi], bf[ni][0], bf[ni][1]);
        }
    }

#pragma unroll
    for (int mi = 0; mi < 2; mi++) {
        int row0 = bm0 + wm + mi * 16 + gq;
        int row1 = row0 + 8;
        float b0 = gd.bias[row0], b1 = gd.bias[row1];
#pragma unroll
        for (int ni = 0; ni < 4; ni++) {
            int col = bn0 + wn + ni * 8 + tg * 2;
            size_t i0 = (size_t)row0 * NSEQ + col;
            size_t i1 = (size_t)row1 * NSEQ + col;
            float v00 = acc[mi][ni][0] + b0, v01 = acc[mi][ni][1] + b0;
            float v10 = acc[mi][ni][2] + b1, v11 = acc[mi][ni][3] + b1;
            if (gd.R) {
                v00 += gd.R[i0]; v01 += gd.R[i0 + 1];
                v10 += gd.R[i1]; v11 += gd.R[i1 + 1];
            }
            if (gd.Y) {
                gd.Y[i0] = v00; gd.Y[i0 + 1] = v01;
                gd.Y[i1] = v10; gd.Y[i1 + 1] = v11;
            }
            if (gd.Ybf) {
                *(__nv_bfloat162*)&gd.Ybf[i0] = bf2(v00, v01);
                *(__nv_bfloat162*)&gd.Ybf[i1] = bf2(v10, v11);
            }
            if (gd.Ytf) {
                gd.Ytf[(size_t)(col + 0) * DMODEL + row0] = __float2bfloat16_rn(v00);
                gd.Ytf[(size_t)(col + 1) * DMODEL + row0] = __float2bfloat16_rn(v01);
                gd.Ytf[(size_t)(col + 0) * DMODEL + row1] = __float2bfloat16_rn(v10);
                gd.Ytf[(size_t)(col + 1) * DMODEL + row1] = __float2bfloat16_rn(v11);
            }
        }
    }
}

// ---------------- bf16 flash attention (R15 configuration — best measured) --
#define QSCALE (0.125f * 1.4426950408889634f)   // 1/sqrt(64) * log2(e)
constexpr int HC = 512;                          // columns per KV pass
constexpr int SMEM_FLASH = 32768;                // Ks2 16KB + Vs 16KB

__global__ __launch_bounds__(256, 4) void flash_kernel(const __nv_bfloat16* __restrict__ Qb,
                                                       const __nv_bfloat16* __restrict__ Kb,
                                                       const __nv_bfloat16* __restrict__ Vb,
                                                       __nv_bfloat16* __restrict__ XTb) {
    extern __shared__ uint32_t fsm[];
    uint32_t* Ks2 = fsm;             // [8][512] words; 16B-chunk swizzle ^((h2&3)<<1)
    uint32_t* Vs  = fsm + 8 * 512;   // [16][256] words; 16B-chunk swizzle ^(h&7)
    const uint32_t ksbase = (uint32_t)__cvta_generic_to_shared(Ks2);
    const uint32_t vsbase = (uint32_t)__cvta_generic_to_shared(Vs);

    const int item = blockIdx.z;
    const int d    = blockIdx.x;
    const int nb   = blockIdx.y * 256;
    const int tid  = threadIdx.x;
    const int warp = tid >> 5;
    const int lane = tid & 31;
    const int gq   = lane >> 2;
    const int tg   = lane & 3;

    const __nv_bfloat16* Qg = Qb + (size_t)item * MN + (size_t)(d * 16) * NSEQ;
    const __nv_bfloat16* Kg = Kb + (size_t)item * MN + (size_t)(d * 16) * NSEQ;
    const __nv_bfloat16* Vg = Vb + (size_t)item * MN + (size_t)(d * 16) * NSEQ;
    __nv_bfloat16* XT = XTb + (size_t)item * MN;

    uint32_t qf[2][4];
#pragma unroll
    for (int mt = 0; mt < 2; mt++) {
        int n0 = nb + warp * 32 + mt * 16 + gq;
        int h0 = 2 * tg;
#pragma unroll
        for (int kb = 0; kb < 2; kb++) {
            int h = h0 + kb * 8;
            float a0 = __bfloat162float(Qg[(size_t)h * NSEQ + n0]) * QSCALE;
            float a1 = __bfloat162float(Qg[(size_t)(h + 1) * NSEQ + n0]) * QSCALE;
            float b0 = __bfloat162float(Qg[(size_t)h * NSEQ + n0 + 8]) * QSCALE;
            float b1 = __bfloat162float(Qg[(size_t)(h + 1) * NSEQ + n0 + 8]) * QSCALE;
            qf[mt][kb * 2 + 0] = packbf(a0, a1);
            qf[mt][kb * 2 + 1] = packbf(b0, b1);
        }
    }

    float xacc[2][2][4];
#pragma unroll
    for (int mt = 0; mt < 2; mt++)
#pragma unroll
        for (int ht = 0; ht < 2; ht++)
#pragma unroll
            for (int r = 0; r < 4; r++) xacc[mt][ht][r] = 0.f;
    float l[4] = {0.f, 0.f, 0.f, 0.f};

    const uint32_t kR0 = ksbase + (tg * 512) * 4 + (gq & 3) * 4;
    const uint32_t kR1 = ksbase + ((tg + 4) * 512) * 4 + (gq & 3) * 4;
    const uint32_t vR0 = vsbase + (gq * 256) * 4 + tg * 4;
    const uint32_t vR1 = vsbase + ((8 + gq) * 256) * 4 + tg * 4;
    const int ksw = tg << 1;
    const int g2  = gq >> 2;
    const int vsw = gq & 7;

#pragma unroll 1
    for (int half = 0; half < 2; half++) {
#pragma unroll
        for (int j = 0; j < 4; j++) {
            int idx = tid + j * 256;
            int h2 = idx >> 7;
            int mc = idx & 127;
            int m = half * HC + mc * 4;
            uint2 uA = *(const uint2*)(Kg + (size_t)(2 * h2) * NSEQ + m);
            uint2 uB = *(const uint2*)(Kg + (size_t)(2 * h2 + 1) * NSEQ + m);
            uint4 o;
            o.x = __byte_perm(uA.x, uB.x, 0x5410);
            o.y = __byte_perm(uA.x, uB.x, 0x7632);
            o.z = __byte_perm(uA.y, uB.y, 0x5410);
            o.w = __byte_perm(uA.y, uB.y, 0x7632);
            *(uint4*)(Ks2 + h2 * 512 + ((mc ^ ((h2 & 3) << 1)) << 2)) = o;
        }
#pragma unroll
        for (int j = 0; j < 4; j++) {
            int idx = tid + j * 256;
            int h = idx >> 6;
            int mc = idx & 63;
            int m = half * HC + mc * 8;
            uint4 v = *(const uint4*)(Vg + (size_t)h * NSEQ + m);
            *(uint4*)(Vs + h * 256 + ((mc ^ (h & 7)) << 2)) = v;
        }
        __syncthreads();

#pragma unroll 2
        for (int m0 = 0; m0 < HC; m0 += 16) {
            int kc0 = ((((m0) >> 2) | g2) ^ ksw) << 4;
            int kc1 = ((((m0 + 8) >> 2) | g2) ^ ksw) << 4;
            uint32_t kb00, kb01, kb10, kb11;
            asm volatile("ld.shared.b32 %0, [%1];" : "=r"(kb00) : "r"(kR0 + kc0));
            asm volatile("ld.shared.b32 %0, [%1];" : "=r"(kb01) : "r"(kR1 + kc0));
            asm volatile("ld.shared.b32 %0, [%1];" : "=r"(kb10) : "r"(kR0 + kc1));
            asm volatile("ld.shared.b32 %0, [%1];" : "=r"(kb11) : "r"(kR1 + kc1));

            int c0 = m0 >> 3;
            int vc0 = ((c0 ^ vsw) << 4);
            int vc1 = (((c0 + 1) ^ vsw) << 4);
            uint32_t vb00, vb01, vb10, vb11;
            asm volatile("ld.shared.b32 %0, [%1];" : "=r"(vb00) : "r"(vR0 + vc0));
            asm volatile("ld.shared.b32 %0, [%1];" : "=r"(vb01) : "r"(vR0 + vc1));
            asm volatile("ld.shared.b32 %0, [%1];" : "=r"(vb10) : "r"(vR1 + vc0));
            asm volatile("ld.shared.b32 %0, [%1];" : "=r"(vb11) : "r"(vR1 + vc1));

#pragma unroll
            for (int mt = 0; mt < 2; mt++) {
                float s0[4] = {0.f, 0.f, 0.f, 0.f};
                float s1[4] = {0.f, 0.f, 0.f, 0.f};
                mma_bf16(s0, qf[mt], kb00, kb01);
                mma_bf16(s1, qf[mt], kb10, kb11);

                float p00 = ex2f(s0[0]), p01 = ex2f(s0[1]);
                float p02 = ex2f(s0[2]), p03 = ex2f(s0[3]);
                float p10 = ex2f(s1[0]), p11 = ex2f(s1[1]);
                float p12 = ex2f(s1[2]), p13 = ex2f(s1[3]);
                l[mt * 2 + 0] += (p00 + p01) + (p10 + p11);
                l[mt * 2 + 1] += (p02 + p03) + (p12 + p13);

                uint32_t pa[4];
                pa[0] = packbf(p00, p01);
                pa[1] = packbf(p02, p03);
                pa[2] = packbf(p10, p11);
                pa[3] = packbf(p12, p13);

                mma_bf16(xacc[mt][0], pa, vb00, vb01);
                mma_bf16(xacc[mt][1], pa, vb10, vb11);
            }
        }
        __syncthreads();
    }

#pragma unroll
    for (int i = 0; i < 4; i++) {
        l[i] += __shfl_xor_sync(0xffffffffu, l[i], 1);
        l[i] += __shfl_xor_sync(0xffffffffu, l[i], 2);
    }
#pragma unroll
    for (int mt = 0; mt < 2; mt++) {
        float inv0 = 1.0f / l[mt * 2 + 0];
        float inv1 = 1.0f / l[mt * 2 + 1];
        int n0 = nb + warp * 32 + mt * 16 + gq;
#pragma unroll
        for (int ht = 0; ht < 2; ht++) {
            int h = d * 16 + ht * 8 + 2 * tg;
            *(__nv_bfloat162*)&XT[(size_t)n0 * DMODEL + h] =
                bf2(xacc[mt][ht][0] * inv0, xacc[mt][ht][1] * inv0);
            *(__nv_bfloat162*)&XT[(size_t)(n0 + 8) * DMODEL + h] =
                bf2(xacc[mt][ht][2] * inv1, xacc[mt][ht][3] * inv1);
        }
    }
}

// ---------------- launch ----------------
extern "C" void kernel_launch(void* const* d_in, const int* in_sizes, int n_in,
                              void* d_out, int out_size) {
    (void)in_sizes; (void)n_in; (void)out_size;

    const float* desc0 = (const float*)d_in[0];
    const float* desc1 = (const float*)d_in[1];
    const float* Wq = (const float*)d_in[2]; const float* bq = (const float*)d_in[3];
    const float* Wk = (const float*)d_in[4]; const float* bk = (const float*)d_in[5];
    const float* Wv = (const float*)d_in[6]; const float* bv = (const float*)d_in[7];
    const float* Wm = (const float*)d_in[8]; const float* bm = (const float*)d_in[9];

    float* out0 = (float*)d_out;
    float* out1 = out0 + MN;

    __nv_bfloat16 *Qb, *Kb, *Vb, *Xb, *Wt, *Dt, *Tt;
    cudaGetSymbolAddress((void**)&Qb, g_Q);
    cudaGetSymbolAddress((void**)&Kb, g_K);
    cudaGetSymbolAddress((void**)&Vb, g_V);
    cudaGetSymbolAddress((void**)&Xb, g_X);
    cudaGetSymbolAddress((void**)&Wt, g_W);
    cudaGetSymbolAddress((void**)&Dt, g_D);
    cudaGetSymbolAddress((void**)&Tt, g_T);

    __nv_bfloat16* W0 = Wt;           __nv_bfloat16* W1 = Wt + MN;
    __nv_bfloat16* W2 = Wt + 2 * MN;  __nv_bfloat16* W3 = Wt + 3 * MN;
    __nv_bfloat16* D0 = Dt;           __nv_bfloat16* D1 = Dt + MN;
    __nv_bfloat16* T0 = Tt;           __nv_bfloat16* T1 = Tt + MN;

    cudaFuncSetAttribute(conv_gemm, cudaFuncAttributeMaxDynamicSharedMemorySize, SMEM_CONV);
    cudaFuncSetAttribute(conv_gemm, cudaFuncAttributePreferredSharedMemoryCarveout,
                         cudaSharedmemCarveoutMaxShared);
    cudaFuncSetAttribute(flash_kernel, cudaFuncAttributeMaxDynamicSharedMemorySize, SMEM_FLASH);
    cudaFuncSetAttribute(flash_kernel, cudaFuncAttributePreferredSharedMemoryCarveout,
                         cudaSharedmemCarveoutMaxShared);

    // ---- prep
    CvtBatch cb{};
    cb.s[0] = Wq; cb.d[0] = W0;
    cb.s[1] = Wk; cb.d[1] = W1;
    cb.s[2] = Wv; cb.d[2] = W2;
    cb.s[3] = Wm; cb.d[3] = W3;
    prep_round<<<dim3(1024, 4), 256>>>(cb);
    CvtTBatch ct{};
    ct.s[0] = desc0; ct.d[0] = D0;
    ct.s[1] = desc1; ct.d[1] = D1;
    prep_round_T<<<dim3(32, 32, 2), 256>>>(ct);

    // ---- attn1 (desc0 self) + attn2 (desc1 self): QKV GEMMs -> bf16 direct
    GemmBatch A{};
    A.g[0] = {W0, bq, D0, nullptr, nullptr, nullptr, Qb};
    A.g[1] = {W1, bk, D0, nullptr, nullptr, nullptr, Kb};
    A.g[2] = {W2, bv, D0, nullptr, nullptr, nullptr, Vb};
    A.g[3] = {W0, bq, D1, nullptr, nullptr, nullptr, Qb + MN};
    A.g[4] = {W1, bk, D1, nullptr, nullptr, nullptr, Kb + MN};
    A.g[5] = {W2, bv, D1, nullptr, nullptr, nullptr, Vb + MN};
    conv_gemm<<<dim3(16, 8, 6), 256, SMEM_CONV>>>(A);

    flash_kernel<<<dim3(64, 4, 2), 256, SMEM_FLASH>>>(Qb, Kb, Vb, Xb);

    // d0 = desc0 + Wm@X0 + bm ; d1 = desc1 + Wm@X1 + bm
    GemmBatch C{};
    C.g[0] = {W3, bm, Xb,      desc0, out0, T0, nullptr};
    C.g[1] = {W3, bm, Xb + MN, desc1, out1, T1, nullptr};
    conv_gemm<<<dim3(16, 8, 2), 256, SMEM_CONV>>>(C);

    // ---- attn3: q=d0, kv=d1
    GemmBatch Dq{};
    Dq.g[0] = {W0, bq, T0, nullptr, nullptr, nullptr, Qb};
    Dq.g[1] = {W1, bk, T1, nullptr, nullptr, nullptr, Kb};
    Dq.g[2] = {W2, bv, T1, nullptr, nullptr, nullptr, Vb};
    conv_gemm<<<dim3(16, 8, 3), 256, SMEM_CONV>>>(Dq);

    flash_kernel<<<dim3(64, 4, 1), 256, SMEM_FLASH>>>(Qb, Kb, Vb, Xb);

    // ---- F (d0 += conv(x), refresh T0) merged with attn4's Q GEMM (needs only T1)
    GemmBatch FG{};
    FG.g[0] = {W3, bm, Xb, out0, out0, T0, nullptr};
    FG.g[1] = {W0, bq, T1, nullptr, nullptr, nullptr, Qb};
    conv_gemm<<<dim3(16, 8, 2), 256, SMEM_CONV>>>(FG);

    // ---- attn4 K,V GEMMs (need T0 from F)
    GemmBatch G{};
    G.g[0] = {W1, bk, T0, nullptr, nullptr, nullptr, Kb};
    G.g[1] = {W2, bv, T0, nullptr, nullptr, nullptr, Vb};
    conv_gemm<<<dim3(16, 8, 2), 256, SMEM_CONV>>>(G);

    flash_kernel<<<dim3(64, 4, 1), 256, SMEM_FLASH>>>(Qb, Kb, Vb, Xb);

    GemmBatch I{};
    I.g[0] = {W3, bm, Xb, out1, out1, nullptr, nullptr};
    conv_gemm<<<dim3(16, 8, 1), 256, SMEM_CONV>>>(I);
}